// round 15
// baseline (speedup 1.0000x reference)
#include <cuda_runtime.h>
#include <cuda_fp16.h>
#include <cstdint>

#define B 64
#define IN 1024
#define ID 256
#define NC 32
#define DC 64

// ---------------- static scratch ---------------------------------------------
__device__ __half g_uh[(size_t)B * IN * ID];           // u fp16 [b,i,d]   32 MB
__device__ float  g_spart[B * 16 * ID];                // colsum partials   1 MB
__device__ __half g_wtil[B * NC * ID];                 // w~ fp16
__device__ float  g_vpart[(size_t)B * 16 * NC * ID];   // v partials       32 MB
__device__ __half g_Whg[NC * DC * ID];                 // W fp16 row-major
__device__ __half g_Wtg[NC * ID * DC];                 // W fp16 transposed

// ---------------- helpers ----------------------------------------------------
__device__ __forceinline__ void mma_f16(float* d, const uint32_t* a, const uint32_t* b) {
    asm volatile(
        "mma.sync.aligned.m16n8k16.row.col.f32.f16.f16.f32 "
        "{%0,%1,%2,%3}, {%4,%5,%6,%7}, {%8,%9}, {%0,%1,%2,%3};"
        : "+f"(d[0]), "+f"(d[1]), "+f"(d[2]), "+f"(d[3])
        : "r"(a[0]), "r"(a[1]), "r"(a[2]), "r"(a[3]), "r"(b[0]), "r"(b[1]));
}
__device__ __forceinline__ uint32_t h2u(__half2 h) { return *reinterpret_cast<uint32_t*>(&h); }
__device__ __forceinline__ uint32_t s2u(const void* p) {
    return (uint32_t)__cvta_generic_to_shared(p);
}
__device__ __forceinline__ void ldsm4(uint32_t* r, uint32_t a) {
    asm volatile("ldmatrix.sync.aligned.m8n8.x4.shared.b16 {%0,%1,%2,%3}, [%4];"
                 : "=r"(r[0]), "=r"(r[1]), "=r"(r[2]), "=r"(r[3]) : "r"(a));
}
__device__ __forceinline__ void ldsm4t(uint32_t* r, uint32_t a) {
    asm volatile("ldmatrix.sync.aligned.m8n8.x4.trans.shared.b16 {%0,%1,%2,%3}, [%4];"
                 : "=r"(r[0]), "=r"(r[1]), "=r"(r[2]), "=r"(r[3]) : "r"(a));
}

// ---------------- prep: u -> fp16 + colsum partials; W -> fp16 x2 (merged) ---
__global__ void __launch_bounds__(256) prep_kernel(const float* __restrict__ u,
                                                   const float* __restrict__ W) {
    extern __shared__ char psm[];     // 36864 B
    const int t = threadIdx.x;
    const int p = t >> 3, seg = t & 7;

    if (blockIdx.x < 1024) {
        float (*cs_sh)[256] = (float (*)[256])psm;
        const int ib = blockIdx.x & 15, b = blockIdx.x >> 4;
        const int i0 = ib * 64;

        const float* src = u + ((size_t)b * IN + i0 + 2 * p) * ID + seg * 32;
        float4 q0[8], q1[8];
#pragma unroll
        for (int r = 0; r < 8; r++) q0[r] = ((const float4*)src)[r];
#pragma unroll
        for (int r = 0; r < 8; r++) q1[r] = ((const float4*)(src + ID))[r];

        {
            uint32_t ha[16], hb[16];
#pragma unroll
            for (int r = 0; r < 8; r++) {
                ha[2 * r]     = h2u(__floats2half2_rn(q0[r].x, q0[r].y));
                ha[2 * r + 1] = h2u(__floats2half2_rn(q0[r].z, q0[r].w));
                hb[2 * r]     = h2u(__floats2half2_rn(q1[r].x, q1[r].y));
                hb[2 * r + 1] = h2u(__floats2half2_rn(q1[r].z, q1[r].w));
            }
            uint4* d0 = (uint4*)(g_uh + ((size_t)b * IN + i0 + 2 * p) * ID + seg * 32);
            uint4* d1 = (uint4*)(g_uh + ((size_t)b * IN + i0 + 2 * p + 1) * ID + seg * 32);
#pragma unroll
            for (int q = 0; q < 4; q++) {
                d0[q] = make_uint4(ha[4 * q], ha[4 * q + 1], ha[4 * q + 2], ha[4 * q + 3]);
                d1[q] = make_uint4(hb[4 * q], hb[4 * q + 1], hb[4 * q + 2], hb[4 * q + 3]);
            }
        }

#pragma unroll
        for (int r = 0; r < 8; r++) {
            float4 s4 = make_float4(q0[r].x + q1[r].x, q0[r].y + q1[r].y,
                                    q0[r].z + q1[r].z, q0[r].w + q1[r].w);
            *(float4*)&cs_sh[p][seg * 32 + 4 * r] = s4;
        }
        __syncthreads();
        {
            const int d = t;
            float cs = 0.f;
#pragma unroll
            for (int q = 0; q < 32; q++) cs += cs_sh[q][d];
            g_spart[(b * 16 + ib) * ID + d] = cs;
        }
    } else {
        __half* Wts = (__half*)psm;   // [256][72]
        const int n = blockIdx.x - 1024;

        const float* src = W + ((size_t)n * DC + 2 * p) * ID + seg * 32;
        float4 q0[8], q1[8];
#pragma unroll
        for (int r = 0; r < 8; r++) q0[r] = ((const float4*)src)[r];
#pragma unroll
        for (int r = 0; r < 8; r++) q1[r] = ((const float4*)(src + ID))[r];

        {
            uint32_t ha[16], hb[16];
#pragma unroll
            for (int r = 0; r < 8; r++) {
                ha[2 * r]     = h2u(__floats2half2_rn(q0[r].x, q0[r].y));
                ha[2 * r + 1] = h2u(__floats2half2_rn(q0[r].z, q0[r].w));
                hb[2 * r]     = h2u(__floats2half2_rn(q1[r].x, q1[r].y));
                hb[2 * r + 1] = h2u(__floats2half2_rn(q1[r].z, q1[r].w));
            }
            uint4* d0 = (uint4*)(g_Whg + ((size_t)n * DC + 2 * p) * ID + seg * 32);
            uint4* d1 = (uint4*)(g_Whg + ((size_t)n * DC + 2 * p + 1) * ID + seg * 32);
#pragma unroll
            for (int q = 0; q < 4; q++) {
                d0[q] = make_uint4(ha[4 * q], ha[4 * q + 1], ha[4 * q + 2], ha[4 * q + 3]);
                d1[q] = make_uint4(hb[4 * q], hb[4 * q + 1], hb[4 * q + 2], hb[4 * q + 3]);
            }
        }

#pragma unroll
        for (int r = 0; r < 8; r++) {
            const int d = seg * 32 + 4 * r;
            *(__half2*)&Wts[(d + 0) * 72 + 2 * p] = __floats2half2_rn(q0[r].x, q1[r].x);
            *(__half2*)&Wts[(d + 1) * 72 + 2 * p] = __floats2half2_rn(q0[r].y, q1[r].y);
            *(__half2*)&Wts[(d + 2) * 72 + 2 * p] = __floats2half2_rn(q0[r].z, q1[r].z);
            *(__half2*)&Wts[(d + 3) * 72 + 2 * p] = __floats2half2_rn(q0[r].w, q1[r].w);
        }
        __syncthreads();
        {
            const uint4* srow = (const uint4*)&Wts[t * 72];
            uint4* dst = (uint4*)(g_Wtg + ((size_t)n * ID + t) * DC);
#pragma unroll
            for (int q = 0; q < 8; q++) dst[q] = srow[q];
        }
    }
}

// ---------------- projection: grid (NC, 4 bgroups), 16 batches/block ---------
// smem: Wh [64][264]h @0 | Wt [256][72]h @33792 | Vs [16][264]h @70656
//       Os [16][68]f @79104 | Oh [16][72]h @83456   (total 85760 B)
template <int PHASE>
__global__ void __launch_bounds__(256) proj_kernel(float* __restrict__ out) {
    extern __shared__ char sm[];
    __half* Wh = (__half*)sm;
    __half* Wt = (__half*)(sm + 33792);
    __half* Vs = (__half*)(sm + 70656);
    float*  Os = (float*)(sm + 79104);
    __half* Oh = (__half*)(sm + 83456);

    const int n = blockIdx.x, b_base = blockIdx.y * 16;
    const int t = threadIdx.x, w = t >> 5, l = t & 31;
    const int g = l >> 2, tig = l & 3;

    // copy W (both layouts) from precomputed fp16 globals
    {
        const uint4* src = (const uint4*)(g_Whg + ((size_t)n * DC + (t >> 2)) * ID + (t & 3) * 64);
        uint4* dst = (uint4*)&Wh[(t >> 2) * 264 + (t & 3) * 64];
#pragma unroll
        for (int q = 0; q < 8; q++) dst[q] = src[q];
    }
    {
        const uint4* src = (const uint4*)(g_Wtg + ((size_t)n * ID + t) * DC);
        uint4* dst = (uint4*)&Wt[t * 72];
#pragma unroll
        for (int q = 0; q < 8; q++) dst[q] = src[q];
    }

    // gather Vs [16 b][256 d]: sum partials (colsum for PHASE 0, vpart otherwise)
    {
        const int bl = t >> 4, seg = t & 15;
        const float* base;
        size_t stride;
        if (PHASE == 0) {
            base = g_spart + (size_t)(b_base + bl) * 16 * ID + seg * 16;
            stride = ID;
        } else {
            base = g_vpart + ((size_t)(b_base + bl) * 16 * NC + n) * ID + seg * 16;
            stride = (size_t)NC * ID;
        }
        float acc[16];
#pragma unroll
        for (int k = 0; k < 16; k++) acc[k] = 0.f;
#pragma unroll 4
        for (int q = 0; q < 16; q++) {
            const float4* sp = (const float4*)(base + q * stride);
#pragma unroll
            for (int r = 0; r < 4; r++) {
                float4 v = sp[r];
                acc[4 * r] += v.x; acc[4 * r + 1] += v.y;
                acc[4 * r + 2] += v.z; acc[4 * r + 3] += v.w;
            }
        }
        uint4* dst = (uint4*)&Vs[bl * 264 + seg * 16];
        dst[0] = make_uint4(h2u(__floats2half2_rn(acc[0], acc[1])),
                            h2u(__floats2half2_rn(acc[2], acc[3])),
                            h2u(__floats2half2_rn(acc[4], acc[5])),
                            h2u(__floats2half2_rn(acc[6], acc[7])));
        dst[1] = make_uint4(h2u(__floats2half2_rn(acc[8], acc[9])),
                            h2u(__floats2half2_rn(acc[10], acc[11])),
                            h2u(__floats2half2_rn(acc[12], acc[13])),
                            h2u(__floats2half2_rn(acc[14], acc[15])));
    }
    __syncthreads();

    // mma1 (warps 0-3): O[16b, dc tile 16w..16w+15] = Vs x Wh
    if (w < 4) {
        float f1[2][4];
#pragma unroll
        for (int j = 0; j < 2; j++)
#pragma unroll
            for (int r = 0; r < 4; r++) f1[j][r] = 0.f;
        const uint32_t sA = s2u(Vs) + (l & 15) * 528 + (l >> 4) * 16;
        const uint32_t sB = s2u(Wh) + (16 * w + (l & 7) + 8 * (l >> 4)) * 528 + ((l >> 3) & 1) * 16;
#pragma unroll
        for (int ks = 0; ks < 16; ks++) {
            uint32_t a[4], bb[4];
            ldsm4(a, sA + ks * 32);
            ldsm4(bb, sB + ks * 32);
            mma_f16(f1[0], a, bb);
            mma_f16(f1[1], a, bb + 2);
        }
#pragma unroll
        for (int nt = 0; nt < 2; nt++) {
            const int dc0 = 16 * w + 8 * nt + 2 * tig;
            *(float2*)&Os[g * 68 + dc0] = make_float2(f1[nt][0], f1[nt][1]);
            *(float2*)&Os[(8 + g) * 68 + dc0] = make_float2(f1[nt][2], f1[nt][3]);
        }
    }
    __syncthreads();

    // norms: thread (bl = t>>4, c = t&15) covers 4 dc
    {
        const int bl = t >> 4, c = t & 15;
        float p2 = 0.f;
#pragma unroll
        for (int j = 0; j < 4; j++) {
            float v = Os[bl * 68 + 4 * c + j];
            p2 += v * v;
        }
        p2 += __shfl_xor_sync(0xffffffffu, p2, 1);
        p2 += __shfl_xor_sync(0xffffffffu, p2, 2);
        p2 += __shfl_xor_sync(0xffffffffu, p2, 4);
        p2 += __shfl_xor_sync(0xffffffffu, p2, 8);
        if (PHASE == 2) {
            float sq = p2 + 1e-7f;
            float sc = sqrtf(sq) / (0.5f + sq);
            float4 o4;
            o4.x = sc * Os[bl * 68 + 4 * c];
            o4.y = sc * Os[bl * 68 + 4 * c + 1];
            o4.z = sc * Os[bl * 68 + 4 * c + 2];
            o4.w = sc * Os[bl * 68 + 4 * c + 3];
            *(float4*)&out[((size_t)(b_base + bl) * NC + n) * DC + 4 * c] = o4;
            return;
        }
        const float inv = 1.0f / fmaxf(sqrtf(p2), 1e-12f);
        uint2 pk;
        pk.x = h2u(__floats2half2_rn(Os[bl * 68 + 4 * c] * inv, Os[bl * 68 + 4 * c + 1] * inv));
        pk.y = h2u(__floats2half2_rn(Os[bl * 68 + 4 * c + 2] * inv, Os[bl * 68 + 4 * c + 3] * inv));
        *(uint2*)&Oh[bl * 72 + 4 * c] = pk;
    }
    __syncthreads();

    // mma2 (all warps): w~[16b, d tile 32w..32w+31] = Oh x Wt
    {
        float f2[4][4];
#pragma unroll
        for (int j = 0; j < 4; j++)
#pragma unroll
            for (int r = 0; r < 4; r++) f2[j][r] = 0.f;
        const uint32_t sA2 = s2u(Oh) + (l & 15) * 144 + (l >> 4) * 16;
        const uint32_t sB2 = s2u(Wt) + (32 * w + (l & 7) + 8 * (l >> 4)) * 144 + ((l >> 3) & 1) * 16;
#pragma unroll
        for (int ks = 0; ks < 4; ks++) {
            uint32_t a[4], b0[4], b1[4];
            ldsm4(a, sA2 + ks * 32);
            ldsm4(b0, sB2 + ks * 32);
            ldsm4(b1, sB2 + 16 * 144 + ks * 32);
            mma_f16(f2[0], a, b0); mma_f16(f2[1], a, b0 + 2);
            mma_f16(f2[2], a, b1); mma_f16(f2[3], a, b1 + 2);
        }
#pragma unroll
        for (int nt = 0; nt < 4; nt++) {
            const int d0 = 32 * w + 8 * nt + 2 * tig;
            *(__half2*)&g_wtil[((size_t)(b_base + g) * NC + n) * ID + d0] =
                __floats2half2_rn(f2[nt][0], f2[nt][1]);
            *(__half2*)&g_wtil[((size_t)(b_base + 8 + g) * NC + n) * ID + d0] =
                __floats2half2_rn(f2[nt][2], f2[nt][3]);
        }
    }
}

// ---------------- fused routing: grid (16, 64), one 64-i chunk per block -----
// smem: uh [64][264]h @0 (33792) | wsh [32][264]h @33792 (16896)
//       csh [32][72]h @50688 (4608) | Lsh [64][34]f @55296 (8704) -> 64000 B
__global__ void __launch_bounds__(256, 3) fused_kernel() {
    extern __shared__ char smem[];
    __half* uh = (__half*)smem;
    __half* wsh = (__half*)(smem + 33792);
    __half* csh = (__half*)(smem + 50688);
    float* Lsh = (float*)(smem + 55296);

    const int b = blockIdx.y;
    const int i0 = blockIdx.x * 64;
    const int t = threadIdx.x, w = t >> 5, l = t & 31;
    const int g = l >> 2, tig = l & 3;

    // load w~
    {
        const int n = t >> 3, seg = t & 7;
        const uint4* wp = (const uint4*)(g_wtil + ((size_t)b * NC + n) * ID + seg * 32);
        uint4* ws = (uint4*)&wsh[n * 264 + seg * 32];
        ws[0] = wp[0]; ws[1] = wp[1]; ws[2] = wp[2]; ws[3] = wp[3];
    }
    // copy uh tile
    {
        const int i = t >> 2, c = t & 3;
        const uint4* src = (const uint4*)(g_uh + ((size_t)b * IN + i0 + i) * ID + c * 64);
        uint4* dst = (uint4*)&uh[i * 264 + c * 64];
#pragma unroll
        for (int q = 0; q < 8; q++) dst[q] = src[q];
    }
    __syncthreads();

    const int lA = l & 15;
    const int lAc = (l >> 4) * 16;
    const int lB = (l & 7) + 8 * (l >> 4);
    const int lBc = ((l >> 3) & 1) * 16;

    const uint32_t uhA = s2u(uh) + ((16 * (w >> 1) + lA) * 264) * 2 + lAc;
    const uint32_t wB  = s2u(wsh) + (((w & 1) * 16 + lB) * 264) * 2 + lBc;
    const uint32_t uhT = s2u(uh) + (lB * 264 + 32 * w) * 2 + lBc;
    const uint32_t cB  = s2u(csh) + (lB * 72) * 2 + lBc;

    // logits mma
    {
        float f[2][4];
#pragma unroll
        for (int nt = 0; nt < 2; nt++)
#pragma unroll
            for (int r = 0; r < 4; r++) f[nt][r] = 0.f;
#pragma unroll
        for (int ks = 0; ks < 16; ks++) {
            uint32_t a[4], bb[4];
            ldsm4(a, uhA + ks * 32);
            ldsm4(bb, wB + ks * 32);
            mma_f16(f[0], a, bb);
            mma_f16(f[1], a, bb + 2);
        }
        const int lmt = w >> 1, hh = w & 1;
#pragma unroll
        for (int nt = 0; nt < 2; nt++) {
            const int n0 = hh * 16 + nt * 8 + 2 * tig;
            *(float2*)&Lsh[(16 * lmt + g) * 34 + n0] = make_float2(f[nt][0], f[nt][1]);
            *(float2*)&Lsh[(16 * lmt + 8 + g) * 34 + n0] = make_float2(f[nt][2], f[nt][3]);
        }
    }
    __syncthreads();

    // softmax over n (lane = n); warp w: i rows 8w..8w+7
#pragma unroll
    for (int r8 = 0; r8 < 8; r8++) {
        const int r = w * 8 + r8;
        const float val = Lsh[r * 34 + l];
        float mx = val;
#pragma unroll
        for (int off = 16; off; off >>= 1)
            mx = fmaxf(mx, __shfl_xor_sync(0xffffffffu, mx, off));
        const float e = __expf(val - mx);
        float s = e;
#pragma unroll
        for (int off = 16; off; off >>= 1) s += __shfl_xor_sync(0xffffffffu, s, off);
        csh[l * 72 + r] = __float2half_rn(e / s);
    }
    __syncthreads();

    // accumulation mma: V[d,n] = sum_i uh^T[d,i] * c[n,i]
    float vfr[2][4][4];
#pragma unroll
    for (int s = 0; s < 2; s++)
#pragma unroll
        for (int nt = 0; nt < 4; nt++)
#pragma unroll
            for (int r = 0; r < 4; r++) vfr[s][nt][r] = 0.f;
#pragma unroll
    for (int ks = 0; ks < 4; ks++) {
        uint32_t a0[4], a1[4], c0[4], c1[4];
        ldsm4t(a0, uhT + ks * 8448);
        ldsm4t(a1, uhT + 32 + ks * 8448);
        ldsm4(c0, cB + ks * 32);
        ldsm4(c1, cB + 2304 + ks * 32);
        mma_f16(vfr[0][0], a0, c0); mma_f16(vfr[0][1], a0, c0 + 2);
        mma_f16(vfr[0][2], a0, c1); mma_f16(vfr[0][3], a0, c1 + 2);
        mma_f16(vfr[1][0], a1, c0); mma_f16(vfr[1][1], a1, c0 + 2);
        mma_f16(vfr[1][2], a1, c1); mma_f16(vfr[1][3], a1, c1 + 2);
    }

    // store V partials
    float* vp = g_vpart + (((size_t)b * 16 + blockIdx.x) * NC) * ID;
#pragma unroll
    for (int s = 0; s < 2; s++) {
        const int d0 = 32 * w + 16 * s + g;
#pragma unroll
        for (int nt = 0; nt < 4; nt++) {
            const int n0 = 8 * nt + 2 * tig;
            vp[(size_t)n0 * ID + d0] = vfr[s][nt][0];
            vp[(size_t)(n0 + 1) * ID + d0] = vfr[s][nt][1];
            vp[(size_t)n0 * ID + d0 + 8] = vfr[s][nt][2];
            vp[(size_t)(n0 + 1) * ID + d0 + 8] = vfr[s][nt][3];
        }
    }
}

// ---------------- launch ------------------------------------------------------
extern "C" void kernel_launch(void* const* d_in, const int* in_sizes, int n_in,
                              void* d_out, int out_size) {
    (void)in_sizes; (void)n_in; (void)out_size;
    const float* u = (const float*)d_in[0];   // [64, 1024, 256] fp32
    const float* W = (const float*)d_in[1];   // [2048, 256] fp32
    float* out = (float*)d_out;               // [64, 32, 64] fp32

    const int pbytes = 85760;   // proj smem
    const int fbytes = 64000;   // fused smem
    const int prbytes = 36864;  // prep smem
    static int attr_done = 0;
    if (!attr_done) {
        cudaFuncSetAttribute(proj_kernel<0>, cudaFuncAttributeMaxDynamicSharedMemorySize, pbytes);
        cudaFuncSetAttribute(proj_kernel<1>, cudaFuncAttributeMaxDynamicSharedMemorySize, pbytes);
        cudaFuncSetAttribute(proj_kernel<2>, cudaFuncAttributeMaxDynamicSharedMemorySize, pbytes);
        cudaFuncSetAttribute(fused_kernel, cudaFuncAttributeMaxDynamicSharedMemorySize, fbytes);
        attr_done = 1;
    }

    prep_kernel<<<1024 + NC, 256, prbytes>>>(u, W);     // u + W -> fp16, colsum
    proj_kernel<0><<<dim3(NC, 4), 256, pbytes>>>(out);  // o0 -> w~0
    fused_kernel<<<dim3(16, B), 256, fbytes>>>();       // iter 1 -> v1
    proj_kernel<1><<<dim3(NC, 4), 256, pbytes>>>(out);  // o1 -> w~1
    fused_kernel<<<dim3(16, B), 256, fbytes>>>();       // iter 2 -> v2
    proj_kernel<2><<<dim3(NC, 4), 256, pbytes>>>(out);  // squash -> out
}

// round 16
// speedup vs baseline: 1.1327x; 1.1327x over previous
#include <cuda_runtime.h>
#include <cuda_fp16.h>
#include <cstdint>

#define B 64
#define IN 1024
#define ID 256
#define NC 32
#define DC 64

// ---------------- static scratch ---------------------------------------------
__device__ __half g_uh[(size_t)B * IN * ID];           // u fp16 [b,i,d]   32 MB
__device__ float  g_spart[B * 16 * ID];                // colsum partials   1 MB
__device__ __half g_s[B * ID];                         // colsum fp16
__device__ __half g_wtil[B * NC * ID];                 // w~ fp16
__device__ __half g_vpart[(size_t)B * 16 * NC * ID];   // v partials fp16  16 MB
__device__ __half g_Whg[NC * DC * ID];                 // W fp16 row-major
__device__ __half g_Wtg[NC * ID * DC];                 // W fp16 transposed

// ---------------- helpers ----------------------------------------------------
__device__ __forceinline__ void mma_f16(float* d, const uint32_t* a, const uint32_t* b) {
    asm volatile(
        "mma.sync.aligned.m16n8k16.row.col.f32.f16.f16.f32 "
        "{%0,%1,%2,%3}, {%4,%5,%6,%7}, {%8,%9}, {%0,%1,%2,%3};"
        : "+f"(d[0]), "+f"(d[1]), "+f"(d[2]), "+f"(d[3])
        : "r"(a[0]), "r"(a[1]), "r"(a[2]), "r"(a[3]), "r"(b[0]), "r"(b[1]));
}
__device__ __forceinline__ uint32_t h2u(__half2 h) { return *reinterpret_cast<uint32_t*>(&h); }
__device__ __forceinline__ uint32_t s2u(const void* p) {
    return (uint32_t)__cvta_generic_to_shared(p);
}
__device__ __forceinline__ void ldsm4(uint32_t* r, uint32_t a) {
    asm volatile("ldmatrix.sync.aligned.m8n8.x4.shared.b16 {%0,%1,%2,%3}, [%4];"
                 : "=r"(r[0]), "=r"(r[1]), "=r"(r[2]), "=r"(r[3]) : "r"(a));
}
__device__ __forceinline__ void ldsm4t(uint32_t* r, uint32_t a) {
    asm volatile("ldmatrix.sync.aligned.m8n8.x4.trans.shared.b16 {%0,%1,%2,%3}, [%4];"
                 : "=r"(r[0]), "=r"(r[1]), "=r"(r[2]), "=r"(r[3]) : "r"(a));
}

// ---------------- prep: u -> fp16 row-major + colsum partials ----------------
__global__ void __launch_bounds__(256, 2) prep_kernel(const float* __restrict__ u) {
    __shared__ float cs_sh[32][256];
    const int ib = blockIdx.x, b = blockIdx.y;
    const int t = threadIdx.x;
    const int p = t >> 3, seg = t & 7;
    const int i0 = ib * 64;

    const float* src = u + ((size_t)b * IN + i0 + 2 * p) * ID + seg * 32;
    float4 q0[8], q1[8];
#pragma unroll
    for (int r = 0; r < 8; r++) q0[r] = ((const float4*)src)[r];
#pragma unroll
    for (int r = 0; r < 8; r++) q1[r] = ((const float4*)(src + ID))[r];

    {
        uint32_t ha[16], hb[16];
#pragma unroll
        for (int r = 0; r < 8; r++) {
            ha[2 * r]     = h2u(__floats2half2_rn(q0[r].x, q0[r].y));
            ha[2 * r + 1] = h2u(__floats2half2_rn(q0[r].z, q0[r].w));
            hb[2 * r]     = h2u(__floats2half2_rn(q1[r].x, q1[r].y));
            hb[2 * r + 1] = h2u(__floats2half2_rn(q1[r].z, q1[r].w));
        }
        uint4* d0 = (uint4*)(g_uh + ((size_t)b * IN + i0 + 2 * p) * ID + seg * 32);
        uint4* d1 = (uint4*)(g_uh + ((size_t)b * IN + i0 + 2 * p + 1) * ID + seg * 32);
#pragma unroll
        for (int q = 0; q < 4; q++) {
            d0[q] = make_uint4(ha[4 * q], ha[4 * q + 1], ha[4 * q + 2], ha[4 * q + 3]);
            d1[q] = make_uint4(hb[4 * q], hb[4 * q + 1], hb[4 * q + 2], hb[4 * q + 3]);
        }
    }

#pragma unroll
    for (int r = 0; r < 8; r++) {
        float4 s4 = make_float4(q0[r].x + q1[r].x, q0[r].y + q1[r].y,
                                q0[r].z + q1[r].z, q0[r].w + q1[r].w);
        *(float4*)&cs_sh[p][seg * 32 + 4 * r] = s4;
    }
    __syncthreads();
    {
        const int d = t;
        float cs = 0.f;
#pragma unroll
        for (int q = 0; q < 32; q++) cs += cs_sh[q][d];
        g_spart[(b * 16 + ib) * ID + d] = cs;
    }
}

// ---------------- colsum reduce -> fp16 ---------------------------------------
__global__ void __launch_bounds__(256) colreduce_kernel() {
    const int b = blockIdx.x, d = threadIdx.x;
    float s = 0.f;
#pragma unroll
    for (int q = 0; q < 16; q++) s += g_spart[(b * 16 + q) * ID + d];
    g_s[b * ID + d] = __float2half_rn(s);
}

// ---------------- wprep: W -> fp16 row-major + transposed (once) -------------
__global__ void __launch_bounds__(256) wprep_kernel(const float* __restrict__ W) {
    __shared__ __half Wts[256 * 72];
    const int n = blockIdx.x;
    const int t = threadIdx.x;
    const int p = t >> 3, seg = t & 7;

    const float* src = W + ((size_t)n * DC + 2 * p) * ID + seg * 32;
    float4 q0[8], q1[8];
#pragma unroll
    for (int r = 0; r < 8; r++) q0[r] = ((const float4*)src)[r];
#pragma unroll
    for (int r = 0; r < 8; r++) q1[r] = ((const float4*)(src + ID))[r];

    // row-major fp16
    {
        uint32_t ha[16], hb[16];
#pragma unroll
        for (int r = 0; r < 8; r++) {
            ha[2 * r]     = h2u(__floats2half2_rn(q0[r].x, q0[r].y));
            ha[2 * r + 1] = h2u(__floats2half2_rn(q0[r].z, q0[r].w));
            hb[2 * r]     = h2u(__floats2half2_rn(q1[r].x, q1[r].y));
            hb[2 * r + 1] = h2u(__floats2half2_rn(q1[r].z, q1[r].w));
        }
        uint4* d0 = (uint4*)(g_Whg + ((size_t)n * DC + 2 * p) * ID + seg * 32);
        uint4* d1 = (uint4*)(g_Whg + ((size_t)n * DC + 2 * p + 1) * ID + seg * 32);
#pragma unroll
        for (int q = 0; q < 4; q++) {
            d0[q] = make_uint4(ha[4 * q], ha[4 * q + 1], ha[4 * q + 2], ha[4 * q + 3]);
            d1[q] = make_uint4(hb[4 * q], hb[4 * q + 1], hb[4 * q + 2], hb[4 * q + 3]);
        }
    }

    // transposed via smem
#pragma unroll
    for (int r = 0; r < 8; r++) {
        const int d = seg * 32 + 4 * r;
        *(__half2*)&Wts[(d + 0) * 72 + 2 * p] = __floats2half2_rn(q0[r].x, q1[r].x);
        *(__half2*)&Wts[(d + 1) * 72 + 2 * p] = __floats2half2_rn(q0[r].y, q1[r].y);
        *(__half2*)&Wts[(d + 2) * 72 + 2 * p] = __floats2half2_rn(q0[r].z, q1[r].z);
        *(__half2*)&Wts[(d + 3) * 72 + 2 * p] = __floats2half2_rn(q0[r].w, q1[r].w);
    }
    __syncthreads();
    {
        const uint4* srow = (const uint4*)&Wts[t * 72];
        uint4* dst = (uint4*)(g_Wtg + ((size_t)n * ID + t) * DC);
#pragma unroll
        for (int q = 0; q < 8; q++) dst[q] = srow[q];
    }
}

// ---------------- projection: grid (NC, 4 bgroups), 16 batches/block ---------
// smem: Wh [64][264]h @0 | Wt [256][72]h @33792 | Vs [16][264]h @70656
//       Os [16][68]f @79104 | Oh [16][72]h @83456   (total 85760 B)
template <int PHASE>
__global__ void __launch_bounds__(256) proj_kernel(float* __restrict__ out) {
    extern __shared__ char sm[];
    __half* Wh = (__half*)sm;
    __half* Wt = (__half*)(sm + 33792);
    __half* Vs = (__half*)(sm + 70656);
    float*  Os = (float*)(sm + 79104);
    __half* Oh = (__half*)(sm + 83456);

    const int n = blockIdx.x, b_base = blockIdx.y * 16;
    const int t = threadIdx.x, w = t >> 5, l = t & 31;
    const int g = l >> 2, tig = l & 3;

    // copy W (both layouts) from precomputed fp16 globals
    {
        const uint4* src = (const uint4*)(g_Whg + ((size_t)n * DC + (t >> 2)) * ID + (t & 3) * 64);
        uint4* dst = (uint4*)&Wh[(t >> 2) * 264 + (t & 3) * 64];
#pragma unroll
        for (int q = 0; q < 8; q++) dst[q] = src[q];
    }
    {
        const uint4* src = (const uint4*)(g_Wtg + ((size_t)n * ID + t) * DC);
        uint4* dst = (uint4*)&Wt[t * 72];
#pragma unroll
        for (int q = 0; q < 8; q++) dst[q] = src[q];
    }

    // gather Vs [16 b][256 d]
    {
        const int bl = t >> 4, seg = t & 15;
        if (PHASE == 0) {
            // colsum fp16: direct copy
            const uint4* src = (const uint4*)(g_s + (b_base + bl) * ID + seg * 16);
            uint4* dst = (uint4*)&Vs[bl * 264 + seg * 16];
            dst[0] = src[0]; dst[1] = src[1];
        } else {
            // fp16 vpart: 16 chunks x 32B (16 halves) per thread
            const __half* base = g_vpart + ((size_t)(b_base + bl) * 16 * NC + n) * ID + seg * 16;
            const size_t stride = (size_t)NC * ID;
            float acc[16];
#pragma unroll
            for (int k = 0; k < 16; k++) acc[k] = 0.f;
#pragma unroll 4
            for (int q = 0; q < 16; q++) {
                const uint4* sp = (const uint4*)(base + q * stride);
                uint4 v0 = sp[0], v1 = sp[1];
                const uint32_t wbuf[8] = {v0.x, v0.y, v0.z, v0.w, v1.x, v1.y, v1.z, v1.w};
#pragma unroll
                for (int k = 0; k < 8; k++) {
                    float2 f = __half22float2(*(const __half2*)&wbuf[k]);
                    acc[2 * k] += f.x;
                    acc[2 * k + 1] += f.y;
                }
            }
            uint4* dst = (uint4*)&Vs[bl * 264 + seg * 16];
            dst[0] = make_uint4(h2u(__floats2half2_rn(acc[0], acc[1])),
                                h2u(__floats2half2_rn(acc[2], acc[3])),
                                h2u(__floats2half2_rn(acc[4], acc[5])),
                                h2u(__floats2half2_rn(acc[6], acc[7])));
            dst[1] = make_uint4(h2u(__floats2half2_rn(acc[8], acc[9])),
                                h2u(__floats2half2_rn(acc[10], acc[11])),
                                h2u(__floats2half2_rn(acc[12], acc[13])),
                                h2u(__floats2half2_rn(acc[14], acc[15])));
        }
    }
    __syncthreads();

    // mma1 (warps 0-3): O[16b, dc tile 16w..16w+15] = Vs x Wh
    const int mt = w >> 1, h = w & 1;
    if (w < 4) {
        float f1[2][4];
#pragma unroll
        for (int j = 0; j < 2; j++)
#pragma unroll
            for (int r = 0; r < 4; r++) f1[j][r] = 0.f;
        const uint32_t sA = s2u(Vs) + (l & 15) * 528 + (l >> 4) * 16;
        const uint32_t sB = s2u(Wh) + (16 * w + (l & 7) + 8 * (l >> 4)) * 528 + ((l >> 3) & 1) * 16;
#pragma unroll
        for (int ks = 0; ks < 16; ks++) {
            uint32_t a[4], bb[4];
            ldsm4(a, sA + ks * 32);
            ldsm4(bb, sB + ks * 32);
            mma_f16(f1[0], a, bb);
            mma_f16(f1[1], a, bb + 2);
        }
#pragma unroll
        for (int nt = 0; nt < 2; nt++) {
            const int dc0 = 16 * w + 8 * nt + 2 * tig;
            *(float2*)&Os[g * 68 + dc0] = make_float2(f1[nt][0], f1[nt][1]);
            *(float2*)&Os[(8 + g) * 68 + dc0] = make_float2(f1[nt][2], f1[nt][3]);
        }
    }
    __syncthreads();

    // norms: thread (bl = t>>4, c = t&15) covers 4 dc
    {
        const int bl = t >> 4, c = t & 15;
        float p2 = 0.f;
#pragma unroll
        for (int j = 0; j < 4; j++) {
            float v = Os[bl * 68 + 4 * c + j];
            p2 += v * v;
        }
        p2 += __shfl_xor_sync(0xffffffffu, p2, 1);
        p2 += __shfl_xor_sync(0xffffffffu, p2, 2);
        p2 += __shfl_xor_sync(0xffffffffu, p2, 4);
        p2 += __shfl_xor_sync(0xffffffffu, p2, 8);
        if (PHASE == 2) {
            float sq = p2 + 1e-7f;
            float sc = sqrtf(sq) / (0.5f + sq);
            float4 o4;
            o4.x = sc * Os[bl * 68 + 4 * c];
            o4.y = sc * Os[bl * 68 + 4 * c + 1];
            o4.z = sc * Os[bl * 68 + 4 * c + 2];
            o4.w = sc * Os[bl * 68 + 4 * c + 3];
            *(float4*)&out[((size_t)(b_base + bl) * NC + n) * DC + 4 * c] = o4;
            return;
        }
        const float inv = 1.0f / fmaxf(sqrtf(p2), 1e-12f);
        uint2 pk;
        pk.x = h2u(__floats2half2_rn(Os[bl * 68 + 4 * c] * inv, Os[bl * 68 + 4 * c + 1] * inv));
        pk.y = h2u(__floats2half2_rn(Os[bl * 68 + 4 * c + 2] * inv, Os[bl * 68 + 4 * c + 3] * inv));
        *(uint2*)&Oh[bl * 72 + 4 * c] = pk;
    }
    __syncthreads();

    // mma2 (all warps): w~[16b, d tile 32w..32w+31] = Oh x Wt
    {
        float f2[4][4];
#pragma unroll
        for (int j = 0; j < 4; j++)
#pragma unroll
            for (int r = 0; r < 4; r++) f2[j][r] = 0.f;
        const uint32_t sA2 = s2u(Oh) + (l & 15) * 144 + (l >> 4) * 16;
        const uint32_t sB2 = s2u(Wt) + (32 * w + (l & 7) + 8 * (l >> 4)) * 144 + ((l >> 3) & 1) * 16;
#pragma unroll
        for (int ks = 0; ks < 4; ks++) {
            uint32_t a[4], b0[4], b1[4];
            ldsm4(a, sA2 + ks * 32);
            ldsm4(b0, sB2 + ks * 32);
            ldsm4(b1, sB2 + 16 * 144 + ks * 32);
            mma_f16(f2[0], a, b0); mma_f16(f2[1], a, b0 + 2);
            mma_f16(f2[2], a, b1); mma_f16(f2[3], a, b1 + 2);
        }
#pragma unroll
        for (int nt = 0; nt < 4; nt++) {
            const int d0 = 32 * w + 8 * nt + 2 * tig;
            *(__half2*)&g_wtil[((size_t)(b_base + g) * NC + n) * ID + d0] =
                __floats2half2_rn(f2[nt][0], f2[nt][1]);
            *(__half2*)&g_wtil[((size_t)(b_base + 8 + g) * NC + n) * ID + d0] =
                __floats2half2_rn(f2[nt][2], f2[nt][3]);
        }
    }
}

// ---------------- fused routing: grid (16, 64), one 64-i chunk per block -----
// smem: uh [64][264]h @0 (33792) | wsh [32][264]h @33792 (16896)
//       csh [32][72]h @50688 (4608) | Lsh [64][34]f @55296 (8704) -> 64000 B
__global__ void __launch_bounds__(256, 3) fused_kernel() {
    extern __shared__ char smem[];
    __half* uh = (__half*)smem;
    __half* wsh = (__half*)(smem + 33792);
    __half* csh = (__half*)(smem + 50688);
    float* Lsh = (float*)(smem + 55296);

    const int b = blockIdx.y;
    const int i0 = blockIdx.x * 64;
    const int t = threadIdx.x, w = t >> 5, l = t & 31;
    const int g = l >> 2, tig = l & 3;

    // load w~
    {
        const int n = t >> 3, seg = t & 7;
        const uint4* wp = (const uint4*)(g_wtil + ((size_t)b * NC + n) * ID + seg * 32);
        uint4* ws = (uint4*)&wsh[n * 264 + seg * 32];
        ws[0] = wp[0]; ws[1] = wp[1]; ws[2] = wp[2]; ws[3] = wp[3];
    }
    // copy uh tile
    {
        const int i = t >> 2, c = t & 3;
        const uint4* src = (const uint4*)(g_uh + ((size_t)b * IN + i0 + i) * ID + c * 64);
        uint4* dst = (uint4*)&uh[i * 264 + c * 64];
#pragma unroll
        for (int q = 0; q < 8; q++) dst[q] = src[q];
    }
    __syncthreads();

    const int lA = l & 15;
    const int lAc = (l >> 4) * 16;
    const int lB = (l & 7) + 8 * (l >> 4);
    const int lBc = ((l >> 3) & 1) * 16;

    const uint32_t uhA = s2u(uh) + ((16 * (w >> 1) + lA) * 264) * 2 + lAc;
    const uint32_t wB  = s2u(wsh) + (((w & 1) * 16 + lB) * 264) * 2 + lBc;
    const uint32_t uhT = s2u(uh) + (lB * 264 + 32 * w) * 2 + lBc;
    const uint32_t cB  = s2u(csh) + (lB * 72) * 2 + lBc;

    // logits mma
    {
        float f[2][4];
#pragma unroll
        for (int nt = 0; nt < 2; nt++)
#pragma unroll
            for (int r = 0; r < 4; r++) f[nt][r] = 0.f;
#pragma unroll
        for (int ks = 0; ks < 16; ks++) {
            uint32_t a[4], bb[4];
            ldsm4(a, uhA + ks * 32);
            ldsm4(bb, wB + ks * 32);
            mma_f16(f[0], a, bb);
            mma_f16(f[1], a, bb + 2);
        }
        const int lmt = w >> 1, hh = w & 1;
#pragma unroll
        for (int nt = 0; nt < 2; nt++) {
            const int n0 = hh * 16 + nt * 8 + 2 * tig;
            *(float2*)&Lsh[(16 * lmt + g) * 34 + n0] = make_float2(f[nt][0], f[nt][1]);
            *(float2*)&Lsh[(16 * lmt + 8 + g) * 34 + n0] = make_float2(f[nt][2], f[nt][3]);
        }
    }
    __syncthreads();

    // softmax over n (lane = n); warp w: i rows 8w..8w+7
#pragma unroll
    for (int r8 = 0; r8 < 8; r8++) {
        const int r = w * 8 + r8;
        const float val = Lsh[r * 34 + l];
        float mx = val;
#pragma unroll
        for (int off = 16; off; off >>= 1)
            mx = fmaxf(mx, __shfl_xor_sync(0xffffffffu, mx, off));
        const float e = __expf(val - mx);
        float s = e;
#pragma unroll
        for (int off = 16; off; off >>= 1) s += __shfl_xor_sync(0xffffffffu, s, off);
        csh[l * 72 + r] = __float2half_rn(e / s);
    }
    __syncthreads();

    // accumulation mma: V[d,n] = sum_i uh^T[d,i] * c[n,i]
    float vfr[2][4][4];
#pragma unroll
    for (int s = 0; s < 2; s++)
#pragma unroll
        for (int nt = 0; nt < 4; nt++)
#pragma unroll
            for (int r = 0; r < 4; r++) vfr[s][nt][r] = 0.f;
#pragma unroll
    for (int ks = 0; ks < 4; ks++) {
        uint32_t a0[4], a1[4], c0[4], c1[4];
        ldsm4t(a0, uhT + ks * 8448);
        ldsm4t(a1, uhT + 32 + ks * 8448);
        ldsm4(c0, cB + ks * 32);
        ldsm4(c1, cB + 2304 + ks * 32);
        mma_f16(vfr[0][0], a0, c0); mma_f16(vfr[0][1], a0, c0 + 2);
        mma_f16(vfr[0][2], a0, c1); mma_f16(vfr[0][3], a0, c1 + 2);
        mma_f16(vfr[1][0], a1, c0); mma_f16(vfr[1][1], a1, c0 + 2);
        mma_f16(vfr[1][2], a1, c1); mma_f16(vfr[1][3], a1, c1 + 2);
    }

    // store V partials (fp16)
    __half* vp = g_vpart + (((size_t)b * 16 + blockIdx.x) * NC) * ID;
#pragma unroll
    for (int s = 0; s < 2; s++) {
        const int d0 = 32 * w + 16 * s + g;
#pragma unroll
        for (int nt = 0; nt < 4; nt++) {
            const int n0 = 8 * nt + 2 * tig;
            vp[(size_t)n0 * ID + d0] = __float2half_rn(vfr[s][nt][0]);
            vp[(size_t)(n0 + 1) * ID + d0] = __float2half_rn(vfr[s][nt][1]);
            vp[(size_t)n0 * ID + d0 + 8] = __float2half_rn(vfr[s][nt][2]);
            vp[(size_t)(n0 + 1) * ID + d0 + 8] = __float2half_rn(vfr[s][nt][3]);
        }
    }
}

// ---------------- launch ------------------------------------------------------
extern "C" void kernel_launch(void* const* d_in, const int* in_sizes, int n_in,
                              void* d_out, int out_size) {
    (void)in_sizes; (void)n_in; (void)out_size;
    const float* u = (const float*)d_in[0];   // [64, 1024, 256] fp32
    const float* W = (const float*)d_in[1];   // [2048, 256] fp32
    float* out = (float*)d_out;               // [64, 32, 64] fp32

    const int pbytes = 85760;   // proj smem
    const int fbytes = 64000;   // fused smem
    static int attr_done = 0;
    if (!attr_done) {
        cudaFuncSetAttribute(proj_kernel<0>, cudaFuncAttributeMaxDynamicSharedMemorySize, pbytes);
        cudaFuncSetAttribute(proj_kernel<1>, cudaFuncAttributeMaxDynamicSharedMemorySize, pbytes);
        cudaFuncSetAttribute(proj_kernel<2>, cudaFuncAttributeMaxDynamicSharedMemorySize, pbytes);
        cudaFuncSetAttribute(fused_kernel, cudaFuncAttributeMaxDynamicSharedMemorySize, fbytes);
        attr_done = 1;
    }

    prep_kernel<<<dim3(16, B), 256>>>(u);               // u -> fp16 + partials
    wprep_kernel<<<NC, 256>>>(W);                       // W -> fp16 x2 (once)
    colreduce_kernel<<<B, 256>>>();                     // colsum -> fp16
    proj_kernel<0><<<dim3(NC, 4), 256, pbytes>>>(out);  // o0 -> w~0
    fused_kernel<<<dim3(16, B), 256, fbytes>>>();       // iter 1 -> v1
    proj_kernel<1><<<dim3(NC, 4), 256, pbytes>>>(out);  // o1 -> w~1
    fused_kernel<<<dim3(16, B), 256, fbytes>>>();       // iter 2 -> v2
    proj_kernel<2><<<dim3(NC, 4), 256, pbytes>>>(out);  // squash -> out
}

// round 17
// speedup vs baseline: 1.1580x; 1.0223x over previous
#include <cuda_runtime.h>
#include <cuda_fp16.h>
#include <cstdint>

#define B 64
#define IN 1024
#define ID 256
#define NC 32
#define DC 64

// ---------------- static scratch ---------------------------------------------
__device__ __half g_uh[(size_t)B * IN * ID];           // u fp16 [b,i,d]   32 MB
__device__ float  g_spart[B * 16 * ID];                // colsum partials   1 MB
__device__ __half g_s[B * ID];                         // colsum fp16
__device__ __half g_wtil[B * NC * ID];                 // w~ fp16
__device__ __half g_vpart[(size_t)B * 16 * NC * ID];   // v partials fp16  16 MB
__device__ __half g_Whg[NC * DC * ID];                 // W fp16 row-major
__device__ __half g_Wtg[NC * ID * DC];                 // W fp16 transposed

// ---------------- helpers ----------------------------------------------------
__device__ __forceinline__ void mma_f16(float* d, const uint32_t* a, const uint32_t* b) {
    asm volatile(
        "mma.sync.aligned.m16n8k16.row.col.f32.f16.f16.f32 "
        "{%0,%1,%2,%3}, {%4,%5,%6,%7}, {%8,%9}, {%0,%1,%2,%3};"
        : "+f"(d[0]), "+f"(d[1]), "+f"(d[2]), "+f"(d[3])
        : "r"(a[0]), "r"(a[1]), "r"(a[2]), "r"(a[3]), "r"(b[0]), "r"(b[1]));
}
__device__ __forceinline__ uint32_t h2u(__half2 h) { return *reinterpret_cast<uint32_t*>(&h); }
__device__ __forceinline__ uint32_t s2u(const void* p) {
    return (uint32_t)__cvta_generic_to_shared(p);
}
__device__ __forceinline__ void ldsm4(uint32_t* r, uint32_t a) {
    asm volatile("ldmatrix.sync.aligned.m8n8.x4.shared.b16 {%0,%1,%2,%3}, [%4];"
                 : "=r"(r[0]), "=r"(r[1]), "=r"(r[2]), "=r"(r[3]) : "r"(a));
}
__device__ __forceinline__ void ldsm4t(uint32_t* r, uint32_t a) {
    asm volatile("ldmatrix.sync.aligned.m8n8.x4.trans.shared.b16 {%0,%1,%2,%3}, [%4];"
                 : "=r"(r[0]), "=r"(r[1]), "=r"(r[2]), "=r"(r[3]) : "r"(a));
}

// ---------------- prep: u -> fp16 row-major + colsum partials ----------------
__global__ void __launch_bounds__(256, 2) prep_kernel(const float* __restrict__ u) {
    __shared__ float cs_sh[32][256];
    const int ib = blockIdx.x, b = blockIdx.y;
    const int t = threadIdx.x;
    const int p = t >> 3, seg = t & 7;
    const int i0 = ib * 64;

    const float* src = u + ((size_t)b * IN + i0 + 2 * p) * ID + seg * 32;
    float4 q0[8], q1[8];
#pragma unroll
    for (int r = 0; r < 8; r++) q0[r] = ((const float4*)src)[r];
#pragma unroll
    for (int r = 0; r < 8; r++) q1[r] = ((const float4*)(src + ID))[r];

    {
        uint32_t ha[16], hb[16];
#pragma unroll
        for (int r = 0; r < 8; r++) {
            ha[2 * r]     = h2u(__floats2half2_rn(q0[r].x, q0[r].y));
            ha[2 * r + 1] = h2u(__floats2half2_rn(q0[r].z, q0[r].w));
            hb[2 * r]     = h2u(__floats2half2_rn(q1[r].x, q1[r].y));
            hb[2 * r + 1] = h2u(__floats2half2_rn(q1[r].z, q1[r].w));
        }
        uint4* d0 = (uint4*)(g_uh + ((size_t)b * IN + i0 + 2 * p) * ID + seg * 32);
        uint4* d1 = (uint4*)(g_uh + ((size_t)b * IN + i0 + 2 * p + 1) * ID + seg * 32);
#pragma unroll
        for (int q = 0; q < 4; q++) {
            d0[q] = make_uint4(ha[4 * q], ha[4 * q + 1], ha[4 * q + 2], ha[4 * q + 3]);
            d1[q] = make_uint4(hb[4 * q], hb[4 * q + 1], hb[4 * q + 2], hb[4 * q + 3]);
        }
    }

#pragma unroll
    for (int r = 0; r < 8; r++) {
        float4 s4 = make_float4(q0[r].x + q1[r].x, q0[r].y + q1[r].y,
                                q0[r].z + q1[r].z, q0[r].w + q1[r].w);
        *(float4*)&cs_sh[p][seg * 32 + 4 * r] = s4;
    }
    __syncthreads();
    {
        const int d = t;
        float cs = 0.f;
#pragma unroll
        for (int q = 0; q < 32; q++) cs += cs_sh[q][d];
        g_spart[(b * 16 + ib) * ID + d] = cs;
    }
}

// ---------------- aux: W -> fp16 x2 (blocks 0..31) + colsum reduce (32..95) --
__global__ void __launch_bounds__(256) aux_kernel(const float* __restrict__ W) {
    __shared__ __half Wts[256 * 72];
    const int t = threadIdx.x;

    if (blockIdx.x >= NC) {
        // colsum reduce -> fp16
        const int b = blockIdx.x - NC, d = t;
        float s = 0.f;
#pragma unroll
        for (int q = 0; q < 16; q++) s += g_spart[(b * 16 + q) * ID + d];
        g_s[b * ID + d] = __float2half_rn(s);
        return;
    }

    const int n = blockIdx.x;
    const int p = t >> 3, seg = t & 7;

    const float* src = W + ((size_t)n * DC + 2 * p) * ID + seg * 32;
    float4 q0[8], q1[8];
#pragma unroll
    for (int r = 0; r < 8; r++) q0[r] = ((const float4*)src)[r];
#pragma unroll
    for (int r = 0; r < 8; r++) q1[r] = ((const float4*)(src + ID))[r];

    // row-major fp16
    {
        uint32_t ha[16], hb[16];
#pragma unroll
        for (int r = 0; r < 8; r++) {
            ha[2 * r]     = h2u(__floats2half2_rn(q0[r].x, q0[r].y));
            ha[2 * r + 1] = h2u(__floats2half2_rn(q0[r].z, q0[r].w));
            hb[2 * r]     = h2u(__floats2half2_rn(q1[r].x, q1[r].y));
            hb[2 * r + 1] = h2u(__floats2half2_rn(q1[r].z, q1[r].w));
        }
        uint4* d0 = (uint4*)(g_Whg + ((size_t)n * DC + 2 * p) * ID + seg * 32);
        uint4* d1 = (uint4*)(g_Whg + ((size_t)n * DC + 2 * p + 1) * ID + seg * 32);
#pragma unroll
        for (int q = 0; q < 4; q++) {
            d0[q] = make_uint4(ha[4 * q], ha[4 * q + 1], ha[4 * q + 2], ha[4 * q + 3]);
            d1[q] = make_uint4(hb[4 * q], hb[4 * q + 1], hb[4 * q + 2], hb[4 * q + 3]);
        }
    }

    // transposed via smem
#pragma unroll
    for (int r = 0; r < 8; r++) {
        const int d = seg * 32 + 4 * r;
        *(__half2*)&Wts[(d + 0) * 72 + 2 * p] = __floats2half2_rn(q0[r].x, q1[r].x);
        *(__half2*)&Wts[(d + 1) * 72 + 2 * p] = __floats2half2_rn(q0[r].y, q1[r].y);
        *(__half2*)&Wts[(d + 2) * 72 + 2 * p] = __floats2half2_rn(q0[r].z, q1[r].z);
        *(__half2*)&Wts[(d + 3) * 72 + 2 * p] = __floats2half2_rn(q0[r].w, q1[r].w);
    }
    __syncthreads();
    {
        const uint4* srow = (const uint4*)&Wts[t * 72];
        uint4* dst = (uint4*)(g_Wtg + ((size_t)n * ID + t) * DC);
#pragma unroll
        for (int q = 0; q < 8; q++) dst[q] = srow[q];
    }
}

// ---------------- projection: grid (NC, 4 bgroups), 16 batches/block ---------
// smem: Wh [64][264]h @0 | Wt [256][72]h @33792 | Vs [16][264]h @70656
//       Os [16][68]f @79104 | Oh [16][72]h @83456   (total 85760 B)
template <int PHASE>
__global__ void __launch_bounds__(256) proj_kernel(float* __restrict__ out) {
    extern __shared__ char sm[];
    __half* Wh = (__half*)sm;
    __half* Wt = (__half*)(sm + 33792);
    __half* Vs = (__half*)(sm + 70656);
    float*  Os = (float*)(sm + 79104);
    __half* Oh = (__half*)(sm + 83456);

    const int n = blockIdx.x, b_base = blockIdx.y * 16;
    const int t = threadIdx.x, w = t >> 5, l = t & 31;
    const int g = l >> 2, tig = l & 3;

    // copy W (both layouts) from precomputed fp16 globals
    {
        const uint4* src = (const uint4*)(g_Whg + ((size_t)n * DC + (t >> 2)) * ID + (t & 3) * 64);
        uint4* dst = (uint4*)&Wh[(t >> 2) * 264 + (t & 3) * 64];
#pragma unroll
        for (int q = 0; q < 8; q++) dst[q] = src[q];
    }
    {
        const uint4* src = (const uint4*)(g_Wtg + ((size_t)n * ID + t) * DC);
        uint4* dst = (uint4*)&Wt[t * 72];
#pragma unroll
        for (int q = 0; q < 8; q++) dst[q] = src[q];
    }

    // gather Vs [16 b][256 d]
    {
        const int bl = t >> 4, seg = t & 15;
        if (PHASE == 0) {
            const uint4* src = (const uint4*)(g_s + (b_base + bl) * ID + seg * 16);
            uint4* dst = (uint4*)&Vs[bl * 264 + seg * 16];
            dst[0] = src[0]; dst[1] = src[1];
        } else {
            const __half* base = g_vpart + ((size_t)(b_base + bl) * 16 * NC + n) * ID + seg * 16;
            const size_t stride = (size_t)NC * ID;
            float acc[16];
#pragma unroll
            for (int k = 0; k < 16; k++) acc[k] = 0.f;
#pragma unroll 4
            for (int q = 0; q < 16; q++) {
                const uint4* sp = (const uint4*)(base + q * stride);
                uint4 v0 = sp[0], v1 = sp[1];
                const uint32_t wbuf[8] = {v0.x, v0.y, v0.z, v0.w, v1.x, v1.y, v1.z, v1.w};
#pragma unroll
                for (int k = 0; k < 8; k++) {
                    float2 f = __half22float2(*(const __half2*)&wbuf[k]);
                    acc[2 * k] += f.x;
                    acc[2 * k + 1] += f.y;
                }
            }
            uint4* dst = (uint4*)&Vs[bl * 264 + seg * 16];
            dst[0] = make_uint4(h2u(__floats2half2_rn(acc[0], acc[1])),
                                h2u(__floats2half2_rn(acc[2], acc[3])),
                                h2u(__floats2half2_rn(acc[4], acc[5])),
                                h2u(__floats2half2_rn(acc[6], acc[7])));
            dst[1] = make_uint4(h2u(__floats2half2_rn(acc[8], acc[9])),
                                h2u(__floats2half2_rn(acc[10], acc[11])),
                                h2u(__floats2half2_rn(acc[12], acc[13])),
                                h2u(__floats2half2_rn(acc[14], acc[15])));
        }
    }
    __syncthreads();

    // mma1 (warps 0-3): O[16b, dc tile 16w..16w+15] = Vs x Wh
    const int mt = w >> 1, h = w & 1;
    if (w < 4) {
        float f1[2][4];
#pragma unroll
        for (int j = 0; j < 2; j++)
#pragma unroll
            for (int r = 0; r < 4; r++) f1[j][r] = 0.f;
        const uint32_t sA = s2u(Vs) + (l & 15) * 528 + (l >> 4) * 16;
        const uint32_t sB = s2u(Wh) + (16 * w + (l & 7) + 8 * (l >> 4)) * 528 + ((l >> 3) & 1) * 16;
#pragma unroll
        for (int ks = 0; ks < 16; ks++) {
            uint32_t a[4], bb[4];
            ldsm4(a, sA + ks * 32);
            ldsm4(bb, sB + ks * 32);
            mma_f16(f1[0], a, bb);
            mma_f16(f1[1], a, bb + 2);
        }
#pragma unroll
        for (int nt = 0; nt < 2; nt++) {
            const int dc0 = 16 * w + 8 * nt + 2 * tig;
            *(float2*)&Os[g * 68 + dc0] = make_float2(f1[nt][0], f1[nt][1]);
            *(float2*)&Os[(8 + g) * 68 + dc0] = make_float2(f1[nt][2], f1[nt][3]);
        }
    }
    __syncthreads();

    // norms: thread (bl = t>>4, c = t&15) covers 4 dc
    {
        const int bl = t >> 4, c = t & 15;
        float p2 = 0.f;
#pragma unroll
        for (int j = 0; j < 4; j++) {
            float v = Os[bl * 68 + 4 * c + j];
            p2 += v * v;
        }
        p2 += __shfl_xor_sync(0xffffffffu, p2, 1);
        p2 += __shfl_xor_sync(0xffffffffu, p2, 2);
        p2 += __shfl_xor_sync(0xffffffffu, p2, 4);
        p2 += __shfl_xor_sync(0xffffffffu, p2, 8);
        if (PHASE == 2) {
            float sq = p2 + 1e-7f;
            float sc = sqrtf(sq) / (0.5f + sq);
            float4 o4;
            o4.x = sc * Os[bl * 68 + 4 * c];
            o4.y = sc * Os[bl * 68 + 4 * c + 1];
            o4.z = sc * Os[bl * 68 + 4 * c + 2];
            o4.w = sc * Os[bl * 68 + 4 * c + 3];
            *(float4*)&out[((size_t)(b_base + bl) * NC + n) * DC + 4 * c] = o4;
            return;
        }
        const float inv = 1.0f / fmaxf(sqrtf(p2), 1e-12f);
        uint2 pk;
        pk.x = h2u(__floats2half2_rn(Os[bl * 68 + 4 * c] * inv, Os[bl * 68 + 4 * c + 1] * inv));
        pk.y = h2u(__floats2half2_rn(Os[bl * 68 + 4 * c + 2] * inv, Os[bl * 68 + 4 * c + 3] * inv));
        *(uint2*)&Oh[bl * 72 + 4 * c] = pk;
    }
    __syncthreads();

    // mma2 (all warps): w~[16b, d tile 32w..32w+31] = Oh x Wt
    {
        float f2[4][4];
#pragma unroll
        for (int j = 0; j < 4; j++)
#pragma unroll
            for (int r = 0; r < 4; r++) f2[j][r] = 0.f;
        const uint32_t sA2 = s2u(Oh) + (l & 15) * 144 + (l >> 4) * 16;
        const uint32_t sB2 = s2u(Wt) + (32 * w + (l & 7) + 8 * (l >> 4)) * 144 + ((l >> 3) & 1) * 16;
#pragma unroll
        for (int ks = 0; ks < 4; ks++) {
            uint32_t a[4], b0[4], b1[4];
            ldsm4(a, sA2 + ks * 32);
            ldsm4(b0, sB2 + ks * 32);
            ldsm4(b1, sB2 + 16 * 144 + ks * 32);
            mma_f16(f2[0], a, b0); mma_f16(f2[1], a, b0 + 2);
            mma_f16(f2[2], a, b1); mma_f16(f2[3], a, b1 + 2);
        }
#pragma unroll
        for (int nt = 0; nt < 4; nt++) {
            const int d0 = 32 * w + 8 * nt + 2 * tig;
            *(__half2*)&g_wtil[((size_t)(b_base + g) * NC + n) * ID + d0] =
                __floats2half2_rn(f2[nt][0], f2[nt][1]);
            *(__half2*)&g_wtil[((size_t)(b_base + 8 + g) * NC + n) * ID + d0] =
                __floats2half2_rn(f2[nt][2], f2[nt][3]);
        }
    }
}

// ---------------- fused routing: grid (16, 64), one 64-i chunk per block -----
// smem: uh [64][264]h @0 (33792) | wsh [32][264]h @33792 (16896)
//       csh [32][72]h @50688 (4608) | Lsh [64][34]f @55296 (8704) -> 64000 B
// After accum mma, uh region is reused to stage V [32 n][264 d] for
// coalesced fp16 global stores.
__global__ void __launch_bounds__(256, 3) fused_kernel() {
    extern __shared__ char smem[];
    __half* uh = (__half*)smem;
    __half* wsh = (__half*)(smem + 33792);
    __half* csh = (__half*)(smem + 50688);
    float* Lsh = (float*)(smem + 55296);

    const int b = blockIdx.y;
    const int i0 = blockIdx.x * 64;
    const int t = threadIdx.x, w = t >> 5, l = t & 31;
    const int g = l >> 2, tig = l & 3;

    // load w~
    {
        const int n = t >> 3, seg = t & 7;
        const uint4* wp = (const uint4*)(g_wtil + ((size_t)b * NC + n) * ID + seg * 32);
        uint4* ws = (uint4*)&wsh[n * 264 + seg * 32];
        ws[0] = wp[0]; ws[1] = wp[1]; ws[2] = wp[2]; ws[3] = wp[3];
    }
    // copy uh tile
    {
        const int i = t >> 2, c = t & 3;
        const uint4* src = (const uint4*)(g_uh + ((size_t)b * IN + i0 + i) * ID + c * 64);
        uint4* dst = (uint4*)&uh[i * 264 + c * 64];
#pragma unroll
        for (int q = 0; q < 8; q++) dst[q] = src[q];
    }
    __syncthreads();

    const int lA = l & 15;
    const int lAc = (l >> 4) * 16;
    const int lB = (l & 7) + 8 * (l >> 4);
    const int lBc = ((l >> 3) & 1) * 16;

    const uint32_t uhA = s2u(uh) + ((16 * (w >> 1) + lA) * 264) * 2 + lAc;
    const uint32_t wB  = s2u(wsh) + (((w & 1) * 16 + lB) * 264) * 2 + lBc;
    const uint32_t uhT = s2u(uh) + (lB * 264 + 32 * w) * 2 + lBc;
    const uint32_t cB  = s2u(csh) + (lB * 72) * 2 + lBc;

    // logits mma
    {
        float f[2][4];
#pragma unroll
        for (int nt = 0; nt < 2; nt++)
#pragma unroll
            for (int r = 0; r < 4; r++) f[nt][r] = 0.f;
#pragma unroll
        for (int ks = 0; ks < 16; ks++) {
            uint32_t a[4], bb[4];
            ldsm4(a, uhA + ks * 32);
            ldsm4(bb, wB + ks * 32);
            mma_f16(f[0], a, bb);
            mma_f16(f[1], a, bb + 2);
        }
        const int lmt = w >> 1, hh = w & 1;
#pragma unroll
        for (int nt = 0; nt < 2; nt++) {
            const int n0 = hh * 16 + nt * 8 + 2 * tig;
            *(float2*)&Lsh[(16 * lmt + g) * 34 + n0] = make_float2(f[nt][0], f[nt][1]);
            *(float2*)&Lsh[(16 * lmt + 8 + g) * 34 + n0] = make_float2(f[nt][2], f[nt][3]);
        }
    }
    __syncthreads();

    // softmax over n (lane = n); warp w: i rows 8w..8w+7
#pragma unroll
    for (int r8 = 0; r8 < 8; r8++) {
        const int r = w * 8 + r8;
        const float val = Lsh[r * 34 + l];
        float mx = val;
#pragma unroll
        for (int off = 16; off; off >>= 1)
            mx = fmaxf(mx, __shfl_xor_sync(0xffffffffu, mx, off));
        const float e = __expf(val - mx);
        float s = e;
#pragma unroll
        for (int off = 16; off; off >>= 1) s += __shfl_xor_sync(0xffffffffu, s, off);
        csh[l * 72 + r] = __float2half_rn(e / s);
    }
    __syncthreads();

    // accumulation mma: V[d,n] = sum_i uh^T[d,i] * c[n,i]
    float vfr[2][4][4];
#pragma unroll
    for (int s = 0; s < 2; s++)
#pragma unroll
        for (int nt = 0; nt < 4; nt++)
#pragma unroll
            for (int r = 0; r < 4; r++) vfr[s][nt][r] = 0.f;
#pragma unroll
    for (int ks = 0; ks < 4; ks++) {
        uint32_t a0[4], a1[4], c0[4], c1[4];
        ldsm4t(a0, uhT + ks * 8448);
        ldsm4t(a1, uhT + 32 + ks * 8448);
        ldsm4(c0, cB + ks * 32);
        ldsm4(c1, cB + 2304 + ks * 32);
        mma_f16(vfr[0][0], a0, c0); mma_f16(vfr[0][1], a0, c0 + 2);
        mma_f16(vfr[0][2], a0, c1); mma_f16(vfr[0][3], a0, c1 + 2);
        mma_f16(vfr[1][0], a1, c0); mma_f16(vfr[1][1], a1, c0 + 2);
        mma_f16(vfr[1][2], a1, c1); mma_f16(vfr[1][3], a1, c1 + 2);
    }
    __syncthreads();   // all reads of uh done -> reuse as V stage [32 n][264 d]

    // stage V fragments into smem (fp16)
    {
        __half* stage = uh;
#pragma unroll
        for (int s = 0; s < 2; s++) {
            const int d0 = 32 * w + 16 * s + g;
#pragma unroll
            for (int nt = 0; nt < 4; nt++) {
                const int n0 = 8 * nt + 2 * tig;
                stage[n0 * 264 + d0]           = __float2half_rn(vfr[s][nt][0]);
                stage[(n0 + 1) * 264 + d0]     = __float2half_rn(vfr[s][nt][1]);
                stage[n0 * 264 + d0 + 8]       = __float2half_rn(vfr[s][nt][2]);
                stage[(n0 + 1) * 264 + d0 + 8] = __float2half_rn(vfr[s][nt][3]);
            }
        }
    }
    __syncthreads();

    // coalesced store: thread (n = t>>3, seg = t&7) writes 32 contiguous halves
    {
        const int n = t >> 3, seg = t & 7;
        const uint4* srow = (const uint4*)&uh[n * 264 + seg * 32];
        uint4* dst = (uint4*)(g_vpart + (((size_t)b * 16 + blockIdx.x) * NC + n) * ID + seg * 32);
        dst[0] = srow[0]; dst[1] = srow[1]; dst[2] = srow[2]; dst[3] = srow[3];
    }
}

// ---------------- launch ------------------------------------------------------
extern "C" void kernel_launch(void* const* d_in, const int* in_sizes, int n_in,
                              void* d_out, int out_size) {
    (void)in_sizes; (void)n_in; (void)out_size;
    const float* u = (const float*)d_in[0];   // [64, 1024, 256] fp32
    const float* W = (const float*)d_in[1];   // [2048, 256] fp32
    float* out = (float*)d_out;               // [64, 32, 64] fp32

    const int pbytes = 85760;   // proj smem
    const int fbytes = 64000;   // fused smem
    static int attr_done = 0;
    if (!attr_done) {
        cudaFuncSetAttribute(proj_kernel<0>, cudaFuncAttributeMaxDynamicSharedMemorySize, pbytes);
        cudaFuncSetAttribute(proj_kernel<1>, cudaFuncAttributeMaxDynamicSharedMemorySize, pbytes);
        cudaFuncSetAttribute(proj_kernel<2>, cudaFuncAttributeMaxDynamicSharedMemorySize, pbytes);
        cudaFuncSetAttribute(fused_kernel, cudaFuncAttributeMaxDynamicSharedMemorySize, fbytes);
        attr_done = 1;
    }

    prep_kernel<<<dim3(16, B), 256>>>(u);               // u -> fp16 + partials
    aux_kernel<<<NC + B, 256>>>(W);                     // W -> fp16 x2 + colsum
    proj_kernel<0><<<dim3(NC, 4), 256, pbytes>>>(out);  // o0 -> w~0
    fused_kernel<<<dim3(16, B), 256, fbytes>>>();       // iter 1 -> v1
    proj_kernel<1><<<dim3(NC, 4), 256, pbytes>>>(out);  // o1 -> w~1
    fused_kernel<<<dim3(16, B), 256, fbytes>>>();       // iter 2 -> v2
    proj_kernel<2><<<dim3(NC, 4), 256, pbytes>>>(out);  // squash -> out
}